// round 7
// baseline (speedup 1.0000x reference)
#include <cuda_runtime.h>
#include <cuda_bf16.h>
#include <cuda_fp16.h>
#include <math_constants.h>
#include <cstdint>

#define NN_NODES 20000
#define EE_EDGES 320000
#define FF 128
#define HH1 3

// ---------------- scratch (static device allocations) ----------------
__device__ __align__(16) __half g_h1[NN_NODES * HH1 * FF];  // layer1 projected feats fp16 [N,384]
__device__ __align__(16) __half g_h2[NN_NODES * FF];        // layer2 projected feats fp16 [N,128]
__device__ float g_el1[NN_NODES * 4];          // stride 4 (3 heads + pad)
__device__ float g_er1[NN_NODES * 4];
__device__ float g_el2[NN_NODES];
__device__ float g_er2[NN_NODES];
__device__ int   g_row[NN_NODES + 1];
__device__ int   g_cursor[NN_NODES];
__device__ int   g_srcp[EE_EDGES];
__device__ int   g_bsums[64];
// A operands [M, 2K] = (hi | lo); B operands [NCOLS, 3K] = (Bhi | Blo | Bhi)
__device__ __align__(16) __nv_bfloat16 g_a1cat[NN_NODES * 256];           // [N,256]
__device__ __align__(16) __nv_bfloat16 g_a2cat[(size_t)NN_NODES * 768];  // [N,768]
__device__ __align__(16) __nv_bfloat16 g_b1cat[384 * 384];
__device__ __align__(16) __nv_bfloat16 g_b2cat[128 * 1152];

// ---------------- helpers ----------------
__device__ __forceinline__ uint32_t smem_u32(const void* p) {
    uint32_t a;
    asm("{ .reg .u64 t; cvta.to.shared.u64 t, %1; cvt.u32.u64 %0, t; }" : "=r"(a) : "l"(p));
    return a;
}
#define LDSM_X4(r0, r1, r2, r3, addr) \
    asm volatile("ldmatrix.sync.aligned.m8n8.x4.shared.b16 {%0,%1,%2,%3}, [%4];" \
                 : "=r"(r0), "=r"(r1), "=r"(r2), "=r"(r3) : "r"(addr))

__device__ __forceinline__ void mma16816(float* d, const uint32_t* a, const uint32_t* b) {
    asm volatile(
        "mma.sync.aligned.m16n8k16.row.col.f32.bf16.bf16.f32 "
        "{%0,%1,%2,%3}, {%4,%5,%6,%7}, {%8,%9}, {%0,%1,%2,%3};"
        : "+f"(d[0]), "+f"(d[1]), "+f"(d[2]), "+f"(d[3])
        : "r"(a[0]), "r"(a[1]), "r"(a[2]), "r"(a[3]), "r"(b[0]), "r"(b[1]));
}

// ---------------- bf16 mma.sync GEMM, BK=64, A hi/lo remap, fp16 C, fused el/er ----------------
// C[M,NCOLS](fp16) = A'[M,3K] @ B[NCOLS,3K]^T, A'[.,k'] = A[., k'<K ? k' : k'-K] (A stored [M,2K]).
// blockIdx.y = 128-col chunk = head; emits el[row*st+bn], er[row*st+bn] from fp32 accumulators.
__global__ __launch_bounds__(256) void gemm_mma(const __nv_bfloat16* __restrict__ A,
                                                const __nv_bfloat16* __restrict__ B,
                                                __half* __restrict__ C,
                                                int M, int K, int NCOLS,
                                                const float* __restrict__ al,
                                                const float* __restrict__ ar,
                                                float* __restrict__ el,
                                                float* __restrict__ er, int st) {
    __shared__ __align__(16) uint8_t sA[16384];  // 128 rows x 128B (64 bf16), xor-swizzled
    __shared__ __align__(16) uint8_t sB[16384];
    const int tid = threadIdx.x, lane = tid & 31, wid = tid >> 5;
    const int bm = blockIdx.x, bn = blockIdx.y;
    const int wm = (wid & 1) * 64, wn = (wid >> 1) * 32;
    const uint32_t sAb = smem_u32(sA), sBb = smem_u32(sB);
    const int Kp = 3 * K, Ald = 2 * K;

    float acc[4][4][4];
    #pragma unroll
    for (int i = 0; i < 4; i++)
        #pragma unroll
        for (int j = 0; j < 4; j++)
            #pragma unroll
            for (int q = 0; q < 4; q++) acc[i][j][q] = 0.f;

    const int lrow = ((lane >> 3) & 1) * 8 + (lane & 7);
    const int lch = lane >> 4;

    uint4 avr[4], bvr[4];
    {
        #pragma unroll
        for (int p = 0; p < 4; p++) {
            int g = tid + p * 256, r = g >> 3, c = g & 7;
            int gr = bm * 128 + r;
            avr[p] = (gr < M) ? *(const uint4*)(A + (size_t)gr * Ald + c * 8)
                              : make_uint4(0u, 0u, 0u, 0u);
            bvr[p] = *(const uint4*)(B + (size_t)(bn * 128 + r) * Kp + c * 8);
        }
    }

    for (int k0 = 0; k0 < Kp; k0 += 64) {
        #pragma unroll
        for (int p = 0; p < 4; p++) {
            int g = tid + p * 256, r = g >> 3, c = g & 7;
            uint32_t soff = r * 128 + ((c ^ (r & 7)) << 4);
            *(uint4*)(sA + soff) = avr[p];
            *(uint4*)(sB + soff) = bvr[p];
        }
        __syncthreads();
        if (k0 + 64 < Kp) {
            int kn = k0 + 64;
            int abase = (kn < K) ? kn : kn - K;
            #pragma unroll
            for (int p = 0; p < 4; p++) {
                int g = tid + p * 256, r = g >> 3, c = g & 7;
                int gr = bm * 128 + r;
                avr[p] = (gr < M) ? *(const uint4*)(A + (size_t)gr * Ald + abase + c * 8)
                                  : make_uint4(0u, 0u, 0u, 0u);
                bvr[p] = *(const uint4*)(B + (size_t)(bn * 128 + r) * Kp + kn + c * 8);
            }
        }
        #pragma unroll
        for (int ks = 0; ks < 4; ks++) {
            const int c = ks * 2 + lch;
            uint32_t af[4][4];
            #pragma unroll
            for (int mt = 0; mt < 4; mt++) {
                int r = wm + mt * 16 + lrow;
                uint32_t addr = sAb + r * 128 + ((c ^ (r & 7)) << 4);
                LDSM_X4(af[mt][0], af[mt][1], af[mt][2], af[mt][3], addr);
            }
            uint32_t bf[4][2];
            #pragma unroll
            for (int h = 0; h < 2; h++) {
                int r = wn + h * 16 + lrow;
                uint32_t addr = sBb + r * 128 + ((c ^ (r & 7)) << 4);
                uint32_t t0, t1, t2, t3;
                LDSM_X4(t0, t1, t2, t3, addr);
                bf[h * 2 + 0][0] = t0; bf[h * 2 + 0][1] = t2;
                bf[h * 2 + 1][0] = t1; bf[h * 2 + 1][1] = t3;
            }
            #pragma unroll
            for (int mt = 0; mt < 4; mt++)
                #pragma unroll
                for (int nt = 0; nt < 4; nt++)
                    mma16816(acc[mt][nt], af[mt], bf[nt]);
        }
        __syncthreads();
    }

    // ---- fp16 C write + fused score partials (scores from fp32 accs) ----
    float ps[4][4];
    #pragma unroll
    for (int mt = 0; mt < 4; mt++) {
        int gr0 = bm * 128 + wm + mt * 16 + (lane >> 2);
        float pl0 = 0.f, pr0 = 0.f, pl1 = 0.f, pr1 = 0.f;
        #pragma unroll
        for (int nt = 0; nt < 4; nt++) {
            int col = wn + nt * 8 + (lane & 3) * 2;
            int gc = bn * 128 + col;
            if (gr0 < M)
                *(__half2*)(C + (size_t)gr0 * NCOLS + gc) =
                    __floats2half2_rn(acc[mt][nt][0], acc[mt][nt][1]);
            if (gr0 + 8 < M)
                *(__half2*)(C + (size_t)(gr0 + 8) * NCOLS + gc) =
                    __floats2half2_rn(acc[mt][nt][2], acc[mt][nt][3]);
            float a0 = al[gc], a1 = al[gc + 1];
            float b0 = ar[gc], b1 = ar[gc + 1];
            pl0 += acc[mt][nt][0] * a0 + acc[mt][nt][1] * a1;
            pr0 += acc[mt][nt][0] * b0 + acc[mt][nt][1] * b1;
            pl1 += acc[mt][nt][2] * a0 + acc[mt][nt][3] * a1;
            pr1 += acc[mt][nt][2] * b0 + acc[mt][nt][3] * b1;
        }
        #pragma unroll
        for (int o = 1; o <= 2; o <<= 1) {
            pl0 += __shfl_xor_sync(0xffffffffu, pl0, o);
            pr0 += __shfl_xor_sync(0xffffffffu, pr0, o);
            pl1 += __shfl_xor_sync(0xffffffffu, pl1, o);
            pr1 += __shfl_xor_sync(0xffffffffu, pr1, o);
        }
        ps[mt][0] = pl0; ps[mt][1] = pr0; ps[mt][2] = pl1; ps[mt][3] = pr1;
    }
    __syncthreads();
    float (*s_sl)[4] = (float(*)[4])sA;
    float (*s_sr)[4] = (float(*)[4])(sA + 2048);
    int wn4 = wid >> 1;
    if ((lane & 3) == 0) {
        #pragma unroll
        for (int mt = 0; mt < 4; mt++) {
            int lr0 = wm + mt * 16 + (lane >> 2);
            s_sl[lr0][wn4] = ps[mt][0];
            s_sr[lr0][wn4] = ps[mt][1];
            s_sl[lr0 + 8][wn4] = ps[mt][2];
            s_sr[lr0 + 8][wn4] = ps[mt][3];
        }
    }
    __syncthreads();
    if (tid < 128) {
        int row = bm * 128 + tid;
        if (row < M) {
            float sl = s_sl[tid][0] + s_sl[tid][1] + s_sl[tid][2] + s_sl[tid][3];
            float sr = s_sr[tid][0] + s_sr[tid][1] + s_sr[tid][2] + s_sr[tid][3];
            el[row * st + bn] = sl;
            er[row * st + bn] = sr;
        }
    }
}

// ---------------- merged prep: A1 split + both B operands ----------------
__global__ void prep_all(const float* __restrict__ feats, const float* __restrict__ W1,
                         const float* __restrict__ W2, __nv_bfloat16* __restrict__ a1,
                         __nv_bfloat16* __restrict__ b1, __nv_bfloat16* __restrict__ b2) {
    int i = blockIdx.x * blockDim.x + threadIdx.x;
    const int SA = NN_NODES * FF;
    const int S1 = 384 * 384;
    if (i < SA) {
        int n = i >> 7, k = i & 127;
        float v = feats[i];
        __nv_bfloat16 h = __float2bfloat16(v);
        __nv_bfloat16 l = __float2bfloat16(v - __bfloat162float(h));
        size_t base = (size_t)n * 256 + k;
        a1[base] = h;
        a1[base + 128] = l;
    } else if (i < SA + S1) {
        int j = i - SA;
        int n = j / 384, kp = j % 384;
        int k = kp & 127;
        float v = W1[k * 384 + n];
        __nv_bfloat16 h = __float2bfloat16(v);
        __nv_bfloat16 l = __float2bfloat16(v - __bfloat162float(h));
        b1[j] = (kp < 128) ? h : ((kp < 256) ? l : h);
    } else if (i < SA + S1 + 128 * 1152) {
        int j = i - SA - S1;
        int n = j / 1152, kp = j % 1152;
        int k = kp % 384;
        float v = W2[k * 128 + n];
        __nv_bfloat16 h = __float2bfloat16(v);
        __nv_bfloat16 l = __float2bfloat16(v - __bfloat162float(h));
        b2[j] = (kp < 384) ? h : ((kp < 768) ? l : h);
    }
}

// ---------------- CSR build ----------------
__global__ void zero_counts_k(int* row) {
    int i = blockIdx.x * blockDim.x + threadIdx.x;
    if (i <= NN_NODES) row[i] = 0;
}
__global__ void count_k(const int* __restrict__ dst, int* row) {
    int e = blockIdx.x * blockDim.x + threadIdx.x;
    if (e < EE_EDGES) atomicAdd(&row[dst[e]], 1);
}
__global__ void scan_block_k(int* __restrict__ row, int* __restrict__ bsums, int n) {
    __shared__ int sm[512];
    int i = blockIdx.x * 512 + threadIdx.x;
    int v = (i < n) ? row[i] : 0;
    sm[threadIdx.x] = v;
    __syncthreads();
    #pragma unroll
    for (int off = 1; off < 512; off <<= 1) {
        int t = (threadIdx.x >= off) ? sm[threadIdx.x - off] : 0;
        __syncthreads();
        sm[threadIdx.x] += t;
        __syncthreads();
    }
    int incl = sm[threadIdx.x];
    if (i < n) row[i] = incl - v;
    if (threadIdx.x == 511) bsums[blockIdx.x] = incl;
}
__global__ void scan_add_k(int* __restrict__ row, const int* __restrict__ bsums,
                           int* __restrict__ cursor, int n, int nb) {
    __shared__ int sb[65];
    int tid = threadIdx.x;
    if (tid == 0) sb[0] = 0;
    if (tid < 64) {
        int v = (tid < nb) ? bsums[tid] : 0;
        int lane = tid & 31;
        #pragma unroll
        for (int o = 1; o < 32; o <<= 1) {
            int t = __shfl_up_sync(0xffffffffu, v, o);
            if (lane >= o) v += t;
        }
        sb[tid + 1] = v;
    }
    __syncthreads();
    if (tid >= 32 && tid < 64) sb[tid + 1] += sb[32];
    __syncthreads();
    int i = blockIdx.x * blockDim.x + tid;
    if (i < n) {
        int v = row[i] + sb[i >> 9];
        row[i] = v;
        cursor[i] = v;
    }
    if (i == 0) row[n] = EE_EDGES;
}
__global__ void scatter_k(const int* __restrict__ src, const int* __restrict__ dst,
                          int* cursor, int* __restrict__ srcp) {
    int e = blockIdx.x * blockDim.x + threadIdx.x;
    if (e < EE_EDGES) {
        int p = atomicAdd(&cursor[dst[e]], 1);
        srcp[p] = src[e];
    }
}

// ---------------- aggregation, fp16 gathers, inline exp-weights: warp per (dst, head) ----------------
template <int HEADS, int ST, bool BF16OUT>
__global__ void agg_k(const __half* __restrict__ hfeat, const float* __restrict__ el,
                      const float* __restrict__ er, const float* __restrict__ bias,
                      const int* __restrict__ row, const int* __restrict__ srcp,
                      float* __restrict__ out, __nv_bfloat16* __restrict__ ocat) {
    int wg = (blockIdx.x * blockDim.x + threadIdx.x) >> 5;
    int lane = threadIdx.x & 31;
    if (wg >= NN_NODES * HEADS) return;
    int d = wg / HEADS, h = wg - d * HEADS;
    int s0 = row[d], s1 = row[d + 1];
    float erd = er[d * ST + h];

    float4 acc = make_float4(0.f, 0.f, 0.f, 0.f);
    float den = 0.f;
    #pragma unroll 2
    for (int i = s0; i < s1; ++i) {
        int s = srcp[i];
        float e = el[s * ST + h] + erd;
        e = (e > 0.f) ? e : 0.2f * e;
        float wt = __expf(e);
        den += wt;
        uint2 raw = *(const uint2*)(hfeat + (size_t)s * (HEADS * 128) + h * 128 + lane * 4);
        float2 v0 = __half22float2(*(__half2*)&raw.x);
        float2 v1 = __half22float2(*(__half2*)&raw.y);
        acc.x += wt * v0.x;
        acc.y += wt * v0.y;
        acc.z += wt * v1.x;
        acc.w += wt * v1.y;
    }
    float inv = 1.0f / den;
    float4 b4 = *(const float4*)(bias + h * 128 + lane * 4);
    float r[4] = {acc.x * inv + b4.x, acc.y * inv + b4.y,
                  acc.z * inv + b4.z, acc.w * inv + b4.w};
    if (BF16OUT) {
        __nv_bfloat16 hv[4], lv[4];
        #pragma unroll
        for (int q = 0; q < 4; q++) {
            hv[q] = __float2bfloat16(r[q]);
            lv[q] = __float2bfloat16(r[q] - __bfloat162float(hv[q]));
        }
        size_t base = (size_t)d * 768 + h * 128 + lane * 4;
        *(uint2*)(ocat + base) = *(uint2*)hv;
        *(uint2*)(ocat + base + 384) = *(uint2*)lv;
    } else {
        *(float4*)(out + (size_t)d * (HEADS * 128) + h * 128 + lane * 4) =
            make_float4(r[0], r[1], r[2], r[3]);
    }
}

// ---------------- launch ----------------
static inline int cdiv(int a, int b) { return (a + b - 1) / b; }

extern "C" void kernel_launch(void* const* d_in, const int* in_sizes, int n_in,
                              void* d_out, int out_size) {
    const float* feats   = (const float*)d_in[0];
    const float* W1      = (const float*)d_in[1];
    const float* attn_l1 = (const float*)d_in[2];
    const float* attn_r1 = (const float*)d_in[3];
    const float* bias1   = (const float*)d_in[4];
    const float* W2      = (const float*)d_in[5];
    const float* attn_l2 = (const float*)d_in[6];
    const float* attn_r2 = (const float*)d_in[7];
    const float* bias2   = (const float*)d_in[8];
    const int*   src     = (const int*)d_in[9];
    const int*   dst     = (const int*)d_in[10];
    float* out = (float*)d_out;

    __half *h1, *h2;
    float *el1, *er1, *el2, *er2;
    int *row, *cursor, *srcp, *bsums;
    __nv_bfloat16 *a1cat, *a2cat, *b1cat, *b2cat;
    cudaGetSymbolAddress((void**)&h1, g_h1);
    cudaGetSymbolAddress((void**)&h2, g_h2);
    cudaGetSymbolAddress((void**)&el1, g_el1);
    cudaGetSymbolAddress((void**)&er1, g_er1);
    cudaGetSymbolAddress((void**)&el2, g_el2);
    cudaGetSymbolAddress((void**)&er2, g_er2);
    cudaGetSymbolAddress((void**)&row, g_row);
    cudaGetSymbolAddress((void**)&cursor, g_cursor);
    cudaGetSymbolAddress((void**)&srcp, g_srcp);
    cudaGetSymbolAddress((void**)&bsums, g_bsums);
    cudaGetSymbolAddress((void**)&a1cat, g_a1cat);
    cudaGetSymbolAddress((void**)&a2cat, g_a2cat);
    cudaGetSymbolAddress((void**)&b1cat, g_b1cat);
    cudaGetSymbolAddress((void**)&b2cat, g_b2cat);

    static cudaStream_t s2 = nullptr;
    static cudaEvent_t evFork = nullptr, evJoin = nullptr;
    if (!s2) {
        cudaStreamCreateWithFlags(&s2, cudaStreamNonBlocking);
        cudaEventCreateWithFlags(&evFork, cudaEventDisableTiming);
        cudaEventCreateWithFlags(&evJoin, cudaEventDisableTiming);
    }

    const int nb = cdiv(NN_NODES, 512);

    // fork: CSR build on side stream, overlapping prep + GEMM1
    cudaEventRecord(evFork, 0);
    cudaStreamWaitEvent(s2, evFork, 0);
    zero_counts_k<<<cdiv(NN_NODES + 1, 256), 256, 0, s2>>>(row);
    count_k<<<cdiv(EE_EDGES, 256), 256, 0, s2>>>(dst, row);
    scan_block_k<<<nb, 512, 0, s2>>>(row, bsums, NN_NODES);
    scan_add_k<<<cdiv(NN_NODES, 256), 256, 0, s2>>>(row, bsums, cursor, NN_NODES, nb);
    scatter_k<<<cdiv(EE_EDGES, 256), 256, 0, s2>>>(src, dst, cursor, srcp);
    cudaEventRecord(evJoin, s2);

    // main: prep + layer1 GEMM (scores fused)
    prep_all<<<cdiv(NN_NODES * FF + 384 * 384 + 128 * 1152, 256), 256>>>(
        feats, W1, W2, a1cat, b1cat, b2cat);
    const int gblocks = cdiv(NN_NODES, 128);
    {
        dim3 grid(gblocks, 3);
        gemm_mma<<<grid, 256>>>(a1cat, b1cat, h1, NN_NODES, 128, 384,
                                attn_l1, attn_r1, el1, er1, 4);
    }

    // join: aggregation needs CSR
    cudaStreamWaitEvent(0, evJoin, 0);
    agg_k<HH1, 4, true><<<cdiv(NN_NODES * HH1 * 32, 256), 256>>>(
        h1, el1, er1, bias1, row, srcp, nullptr, a2cat);

    // layer 2
    {
        dim3 grid(gblocks, 1);
        gemm_mma<<<grid, 256>>>(a2cat, b2cat, h2, NN_NODES, 384, 128,
                                attn_l2, attn_r2, el2, er2, 1);
    }
    agg_k<1, 1, false><<<cdiv(NN_NODES * 32, 256), 256>>>(
        h2, el2, er2, bias2, row, srcp, out, nullptr);
}

// round 8
// speedup vs baseline: 1.0737x; 1.0737x over previous
#include <cuda_runtime.h>
#include <cuda_bf16.h>
#include <math_constants.h>
#include <cstdint>

#define NN_NODES 20000
#define EE_EDGES 320000
#define FF 128
#define HH1 3

// ---------------- scratch (static device allocations) ----------------
__device__ float g_h1[NN_NODES * HH1 * FF];    // layer1 projected feats fp32 [N,384]
__device__ float g_h2[NN_NODES * FF];          // layer2 projected feats fp32 [N,128]
__device__ float g_el1[NN_NODES * 4];
__device__ float g_er1[NN_NODES * 4];
__device__ float g_el2[NN_NODES];
__device__ float g_er2[NN_NODES];
__device__ int   g_row[NN_NODES + 1];
__device__ int   g_cursor[NN_NODES];
__device__ int   g_srcp[EE_EDGES];
__device__ int   g_bsums[64];
// A operands [M, 2K] = (hi | lo); B operands [NCOLS, 3K] = (Bhi | Blo | Bhi)
__device__ __align__(16) __nv_bfloat16 g_a1cat[NN_NODES * 256];
__device__ __align__(16) __nv_bfloat16 g_a2cat[(size_t)NN_NODES * 768];
__device__ __align__(16) __nv_bfloat16 g_b1cat[384 * 384];
__device__ __align__(16) __nv_bfloat16 g_b2cat[128 * 1152];

// ---------------- helpers ----------------
__device__ __forceinline__ uint32_t smem_u32(const void* p) {
    uint32_t a;
    asm("{ .reg .u64 t; cvta.to.shared.u64 t, %1; cvt.u32.u64 %0, t; }" : "=r"(a) : "l"(p));
    return a;
}
#define LDSM_X4(r0, r1, r2, r3, addr) \
    asm volatile("ldmatrix.sync.aligned.m8n8.x4.shared.b16 {%0,%1,%2,%3}, [%4];" \
                 : "=r"(r0), "=r"(r1), "=r"(r2), "=r"(r3) : "r"(addr))

__device__ __forceinline__ void mma16816(float* d, const uint32_t* a, const uint32_t* b) {
    asm volatile(
        "mma.sync.aligned.m16n8k16.row.col.f32.bf16.bf16.f32 "
        "{%0,%1,%2,%3}, {%4,%5,%6,%7}, {%8,%9}, {%0,%1,%2,%3};"
        : "+f"(d[0]), "+f"(d[1]), "+f"(d[2]), "+f"(d[3])
        : "r"(a[0]), "r"(a[1]), "r"(a[2]), "r"(a[3]), "r"(b[0]), "r"(b[1]));
}
__device__ __forceinline__ void cp16(uint32_t saddr, const void* g, uint32_t sz) {
    asm volatile("cp.async.cg.shared.global [%0], [%1], 16, %2;"
                 :: "r"(saddr), "l"(g), "r"(sz) : "memory");
}
#define CP_COMMIT() asm volatile("cp.async.commit_group;" ::: "memory")
#define CP_WAIT1()  asm volatile("cp.async.wait_group 1;" ::: "memory")

// ---------------- bf16 mma.sync GEMM, BK=64, cp.async 2-stage, fused el/er ----------------
// C[M,NCOLS] = A'[M,3K] @ B[NCOLS,3K]^T, A'[.,k'] = A[., k'<K ? k' : k'-K] (A stored [M,2K]).
// blockIdx.y = 128-col chunk = head; emits el/er from fp32 accumulators.
__global__ __launch_bounds__(256) void gemm_mma(const __nv_bfloat16* __restrict__ A,
                                                const __nv_bfloat16* __restrict__ B,
                                                float* __restrict__ C,
                                                int M, int K, int NCOLS,
                                                const float* __restrict__ al,
                                                const float* __restrict__ ar,
                                                float* __restrict__ el,
                                                float* __restrict__ er, int st) {
    extern __shared__ __align__(16) uint8_t smem[];  // [2][sA 16K | sB 16K] = 64 KB
    const int tid = threadIdx.x, lane = tid & 31, wid = tid >> 5;
    const int bm = blockIdx.x, bn = blockIdx.y;
    const int wm = (wid & 1) * 64, wn = (wid >> 1) * 32;
    const uint32_t sbase = smem_u32(smem);
    const int Kp = 3 * K, Ald = 2 * K;

    float acc[4][4][4];
    #pragma unroll
    for (int i = 0; i < 4; i++)
        #pragma unroll
        for (int j = 0; j < 4; j++)
            #pragma unroll
            for (int q = 0; q < 4; q++) acc[i][j][q] = 0.f;

    const int lrow = ((lane >> 3) & 1) * 8 + (lane & 7);
    const int lch = lane >> 4;

    // per-thread load coords (4 x 16B per matrix per stage)
    int lr[4], lc[4];
    uint32_t lso[4];
    #pragma unroll
    for (int p = 0; p < 4; p++) {
        int g = tid + p * 256;
        lr[p] = g >> 3;
        lc[p] = g & 7;
        lso[p] = (uint32_t)(lr[p] * 128 + ((lc[p] ^ (lr[p] & 7)) << 4));
    }

    // issue stage for k-offset kn into buffer buf
    auto issue = [&](int buf, int kn) {
        int abase = (kn < K) ? kn : kn - K;
        uint32_t sa = sbase + buf * 32768;
        uint32_t sb = sa + 16384;
        #pragma unroll
        for (int p = 0; p < 4; p++) {
            int gr = bm * 128 + lr[p];
            cp16(sa + lso[p], A + (size_t)gr * Ald + abase + lc[p] * 8,
                 (gr < M) ? 16u : 0u);
            cp16(sb + lso[p], B + (size_t)(bn * 128 + lr[p]) * Kp + kn + lc[p] * 8, 16u);
        }
        CP_COMMIT();
    };

    issue(0, 0);
    issue(1, 64);

    const int nchunks = Kp >> 6;
    for (int ck = 0; ck < nchunks; ck++) {
        int buf = ck & 1;
        CP_WAIT1();
        __syncthreads();
        uint32_t sAb = sbase + buf * 32768;
        uint32_t sBb = sAb + 16384;
        #pragma unroll
        for (int ks = 0; ks < 4; ks++) {
            const int c = ks * 2 + lch;
            uint32_t af[4][4];
            #pragma unroll
            for (int mt = 0; mt < 4; mt++) {
                int r = wm + mt * 16 + lrow;
                uint32_t addr = sAb + r * 128 + ((c ^ (r & 7)) << 4);
                LDSM_X4(af[mt][0], af[mt][1], af[mt][2], af[mt][3], addr);
            }
            uint32_t bf[4][2];
            #pragma unroll
            for (int h = 0; h < 2; h++) {
                int r = wn + h * 16 + lrow;
                uint32_t addr = sBb + r * 128 + ((c ^ (r & 7)) << 4);
                uint32_t t0, t1, t2, t3;
                LDSM_X4(t0, t1, t2, t3, addr);
                bf[h * 2 + 0][0] = t0; bf[h * 2 + 0][1] = t2;
                bf[h * 2 + 1][0] = t1; bf[h * 2 + 1][1] = t3;
            }
            #pragma unroll
            for (int mt = 0; mt < 4; mt++)
                #pragma unroll
                for (int nt = 0; nt < 4; nt++)
                    mma16816(acc[mt][nt], af[mt], bf[nt]);
        }
        __syncthreads();
        if (ck + 2 < nchunks) issue(buf, (ck + 2) * 64);
        else CP_COMMIT();  // keep wait_group accounting
    }

    // ---- C write + fused score partials ----
    float ps[4][4];
    #pragma unroll
    for (int mt = 0; mt < 4; mt++) {
        int gr0 = bm * 128 + wm + mt * 16 + (lane >> 2);
        float pl0 = 0.f, pr0 = 0.f, pl1 = 0.f, pr1 = 0.f;
        #pragma unroll
        for (int nt = 0; nt < 4; nt++) {
            int col = wn + nt * 8 + (lane & 3) * 2;
            int gc = bn * 128 + col;
            if (gr0 < M)
                *(float2*)(C + (size_t)gr0 * NCOLS + gc) =
                    make_float2(acc[mt][nt][0], acc[mt][nt][1]);
            if (gr0 + 8 < M)
                *(float2*)(C + (size_t)(gr0 + 8) * NCOLS + gc) =
                    make_float2(acc[mt][nt][2], acc[mt][nt][3]);
            float a0 = al[gc], a1 = al[gc + 1];
            float b0 = ar[gc], b1 = ar[gc + 1];
            pl0 += acc[mt][nt][0] * a0 + acc[mt][nt][1] * a1;
            pr0 += acc[mt][nt][0] * b0 + acc[mt][nt][1] * b1;
            pl1 += acc[mt][nt][2] * a0 + acc[mt][nt][3] * a1;
            pr1 += acc[mt][nt][2] * b0 + acc[mt][nt][3] * b1;
        }
        #pragma unroll
        for (int o = 1; o <= 2; o <<= 1) {
            pl0 += __shfl_xor_sync(0xffffffffu, pl0, o);
            pr0 += __shfl_xor_sync(0xffffffffu, pr0, o);
            pl1 += __shfl_xor_sync(0xffffffffu, pl1, o);
            pr1 += __shfl_xor_sync(0xffffffffu, pr1, o);
        }
        ps[mt][0] = pl0; ps[mt][1] = pr0; ps[mt][2] = pl1; ps[mt][3] = pr1;
    }
    __syncthreads();
    float (*s_sl)[4] = (float(*)[4])smem;
    float (*s_sr)[4] = (float(*)[4])(smem + 2048);
    int wn4 = wid >> 1;
    if ((lane & 3) == 0) {
        #pragma unroll
        for (int mt = 0; mt < 4; mt++) {
            int lr0 = wm + mt * 16 + (lane >> 2);
            s_sl[lr0][wn4] = ps[mt][0];
            s_sr[lr0][wn4] = ps[mt][1];
            s_sl[lr0 + 8][wn4] = ps[mt][2];
            s_sr[lr0 + 8][wn4] = ps[mt][3];
        }
    }
    __syncthreads();
    if (tid < 128) {
        int row = bm * 128 + tid;
        if (row < M) {
            float sl = s_sl[tid][0] + s_sl[tid][1] + s_sl[tid][2] + s_sl[tid][3];
            float sr = s_sr[tid][0] + s_sr[tid][1] + s_sr[tid][2] + s_sr[tid][3];
            el[row * st + bn] = sl;
            er[row * st + bn] = sr;
        }
    }
}

// ---------------- merged prep ----------------
__global__ void prep_all(const float* __restrict__ feats, const float* __restrict__ W1,
                         const float* __restrict__ W2, __nv_bfloat16* __restrict__ a1,
                         __nv_bfloat16* __restrict__ b1, __nv_bfloat16* __restrict__ b2) {
    int i = blockIdx.x * blockDim.x + threadIdx.x;
    const int SA = NN_NODES * FF;
    const int S1 = 384 * 384;
    if (i < SA) {
        int n = i >> 7, k = i & 127;
        float v = feats[i];
        __nv_bfloat16 h = __float2bfloat16(v);
        __nv_bfloat16 l = __float2bfloat16(v - __bfloat162float(h));
        size_t base = (size_t)n * 256 + k;
        a1[base] = h;
        a1[base + 128] = l;
    } else if (i < SA + S1) {
        int j = i - SA;
        int n = j / 384, kp = j % 384;
        int k = kp & 127;
        float v = W1[k * 384 + n];
        __nv_bfloat16 h = __float2bfloat16(v);
        __nv_bfloat16 l = __float2bfloat16(v - __bfloat162float(h));
        b1[j] = (kp < 128) ? h : ((kp < 256) ? l : h);
    } else if (i < SA + S1 + 128 * 1152) {
        int j = i - SA - S1;
        int n = j / 1152, kp = j % 1152;
        int k = kp % 384;
        float v = W2[k * 128 + n];
        __nv_bfloat16 h = __float2bfloat16(v);
        __nv_bfloat16 l = __float2bfloat16(v - __bfloat162float(h));
        b2[j] = (kp < 384) ? h : ((kp < 768) ? l : h);
    }
}

// ---------------- CSR build ----------------
__global__ void zero_counts_k(int* row) {
    int i = blockIdx.x * blockDim.x + threadIdx.x;
    if (i <= NN_NODES) row[i] = 0;
}
__global__ void count_k(const int* __restrict__ dst, int* row) {
    int e = blockIdx.x * blockDim.x + threadIdx.x;
    if (e < EE_EDGES) atomicAdd(&row[dst[e]], 1);
}
__global__ void scan_block_k(int* __restrict__ row, int* __restrict__ bsums, int n) {
    __shared__ int sm[512];
    int i = blockIdx.x * 512 + threadIdx.x;
    int v = (i < n) ? row[i] : 0;
    sm[threadIdx.x] = v;
    __syncthreads();
    #pragma unroll
    for (int off = 1; off < 512; off <<= 1) {
        int t = (threadIdx.x >= off) ? sm[threadIdx.x - off] : 0;
        __syncthreads();
        sm[threadIdx.x] += t;
        __syncthreads();
    }
    int incl = sm[threadIdx.x];
    if (i < n) row[i] = incl - v;
    if (threadIdx.x == 511) bsums[blockIdx.x] = incl;
}
__global__ void scan_add_k(int* __restrict__ row, const int* __restrict__ bsums,
                           int* __restrict__ cursor, int n, int nb) {
    __shared__ int sb[65];
    int tid = threadIdx.x;
    if (tid == 0) sb[0] = 0;
    if (tid < 64) {
        int v = (tid < nb) ? bsums[tid] : 0;
        int lane = tid & 31;
        #pragma unroll
        for (int o = 1; o < 32; o <<= 1) {
            int t = __shfl_up_sync(0xffffffffu, v, o);
            if (lane >= o) v += t;
        }
        sb[tid + 1] = v;
    }
    __syncthreads();
    if (tid >= 32 && tid < 64) sb[tid + 1] += sb[32];
    __syncthreads();
    int i = blockIdx.x * blockDim.x + tid;
    if (i < n) {
        int v = row[i] + sb[i >> 9];
        row[i] = v;
        cursor[i] = v;
    }
    if (i == 0) row[n] = EE_EDGES;
}
__global__ void scatter_k(const int* __restrict__ src, const int* __restrict__ dst,
                          int* cursor, int* __restrict__ srcp) {
    int e = blockIdx.x * blockDim.x + threadIdx.x;
    if (e < EE_EDGES) {
        int p = atomicAdd(&cursor[dst[e]], 1);
        srcp[p] = src[e];
    }
}

// ---------------- aggregation, fp32 gathers, inline exp-weights: warp per (dst, head) ----------------
template <int HEADS, int ST, bool BF16OUT>
__global__ void agg_k(const float* __restrict__ hfeat, const float* __restrict__ el,
                      const float* __restrict__ er, const float* __restrict__ bias,
                      const int* __restrict__ row, const int* __restrict__ srcp,
                      float* __restrict__ out, __nv_bfloat16* __restrict__ ocat) {
    int wg = (blockIdx.x * blockDim.x + threadIdx.x) >> 5;
    int lane = threadIdx.x & 31;
    if (wg >= NN_NODES * HEADS) return;
    int d = wg / HEADS, h = wg - d * HEADS;
    int s0 = row[d], s1 = row[d + 1];
    float erd = er[d * ST + h];

    float4 acc = make_float4(0.f, 0.f, 0.f, 0.f);
    float den = 0.f;
    #pragma unroll 2
    for (int i = s0; i < s1; ++i) {
        int s = srcp[i];
        float e = el[s * ST + h] + erd;
        e = (e > 0.f) ? e : 0.2f * e;
        float wt = __expf(e);
        den += wt;
        float4 v = *(const float4*)(hfeat + (size_t)s * (HEADS * 128) + h * 128 + lane * 4);
        acc.x += wt * v.x;
        acc.y += wt * v.y;
        acc.z += wt * v.z;
        acc.w += wt * v.w;
    }
    float inv = 1.0f / den;
    float4 b4 = *(const float4*)(bias + h * 128 + lane * 4);
    float r[4] = {acc.x * inv + b4.x, acc.y * inv + b4.y,
                  acc.z * inv + b4.z, acc.w * inv + b4.w};
    if (BF16OUT) {
        __nv_bfloat16 hv[4], lv[4];
        #pragma unroll
        for (int q = 0; q < 4; q++) {
            hv[q] = __float2bfloat16(r[q]);
            lv[q] = __float2bfloat16(r[q] - __bfloat162float(hv[q]));
        }
        size_t base = (size_t)d * 768 + h * 128 + lane * 4;
        *(uint2*)(ocat + base) = *(uint2*)hv;
        *(uint2*)(ocat + base + 384) = *(uint2*)lv;
    } else {
        *(float4*)(out + (size_t)d * (HEADS * 128) + h * 128 + lane * 4) =
            make_float4(r[0], r[1], r[2], r[3]);
    }
}

// ---------------- launch ----------------
static inline int cdiv(int a, int b) { return (a + b - 1) / b; }

extern "C" void kernel_launch(void* const* d_in, const int* in_sizes, int n_in,
                              void* d_out, int out_size) {
    const float* feats   = (const float*)d_in[0];
    const float* W1      = (const float*)d_in[1];
    const float* attn_l1 = (const float*)d_in[2];
    const float* attn_r1 = (const float*)d_in[3];
    const float* bias1   = (const float*)d_in[4];
    const float* W2      = (const float*)d_in[5];
    const float* attn_l2 = (const float*)d_in[6];
    const float* attn_r2 = (const float*)d_in[7];
    const float* bias2   = (const float*)d_in[8];
    const int*   src     = (const int*)d_in[9];
    const int*   dst     = (const int*)d_in[10];
    float* out = (float*)d_out;

    float *h1, *h2, *el1, *er1, *el2, *er2;
    int *row, *cursor, *srcp, *bsums;
    __nv_bfloat16 *a1cat, *a2cat, *b1cat, *b2cat;
    cudaGetSymbolAddress((void**)&h1, g_h1);
    cudaGetSymbolAddress((void**)&h2, g_h2);
    cudaGetSymbolAddress((void**)&el1, g_el1);
    cudaGetSymbolAddress((void**)&er1, g_er1);
    cudaGetSymbolAddress((void**)&el2, g_el2);
    cudaGetSymbolAddress((void**)&er2, g_er2);
    cudaGetSymbolAddress((void**)&row, g_row);
    cudaGetSymbolAddress((void**)&cursor, g_cursor);
    cudaGetSymbolAddress((void**)&srcp, g_srcp);
    cudaGetSymbolAddress((void**)&bsums, g_bsums);
    cudaGetSymbolAddress((void**)&a1cat, g_a1cat);
    cudaGetSymbolAddress((void**)&a2cat, g_a2cat);
    cudaGetSymbolAddress((void**)&b1cat, g_b1cat);
    cudaGetSymbolAddress((void**)&b2cat, g_b2cat);

    static cudaStream_t s2 = nullptr;
    static cudaEvent_t evFork = nullptr, evJoin = nullptr;
    static bool attrDone = false;
    if (!s2) {
        cudaStreamCreateWithFlags(&s2, cudaStreamNonBlocking);
        cudaEventCreateWithFlags(&evFork, cudaEventDisableTiming);
        cudaEventCreateWithFlags(&evJoin, cudaEventDisableTiming);
    }
    if (!attrDone) {
        cudaFuncSetAttribute(gemm_mma, cudaFuncAttributeMaxDynamicSharedMemorySize, 65536);
        attrDone = true;
    }

    const int nb = cdiv(NN_NODES, 512);
    const int gblocks = cdiv(NN_NODES, 128);

    // fork CSR head on side stream
    cudaEventRecord(evFork, 0);
    cudaStreamWaitEvent(s2, evFork, 0);
    zero_counts_k<<<cdiv(NN_NODES + 1, 256), 256, 0, s2>>>(row);             // 1
    count_k<<<cdiv(EE_EDGES, 256), 256, 0, s2>>>(dst, row);                  // 2
    prep_all<<<cdiv(NN_NODES * FF + 384 * 384 + 128 * 1152, 256), 256>>>(    // 3
        feats, W1, W2, a1cat, b1cat, b2cat);
    {
        dim3 grid(gblocks, 3);
        gemm_mma<<<grid, 256, 65536>>>(a1cat, b1cat, h1, NN_NODES, 128, 384, // 4 (profiled)
                                       attn_l1, attn_r1, el1, er1, 4);
    }
    scan_block_k<<<nb, 512, 0, s2>>>(row, bsums, NN_NODES);                  // 5
    scan_add_k<<<cdiv(NN_NODES, 256), 256, 0, s2>>>(row, bsums, cursor, NN_NODES, nb); // 6
    scatter_k<<<cdiv(EE_EDGES, 256), 256, 0, s2>>>(src, dst, cursor, srcp);  // 7
    cudaEventRecord(evJoin, s2);

    cudaStreamWaitEvent(0, evJoin, 0);
    agg_k<HH1, 4, true><<<cdiv(NN_NODES * HH1 * 32, 256), 256>>>(            // 8
        h1, el1, er1, bias1, row, srcp, nullptr, a2cat);

    {
        dim3 grid(gblocks, 1);
        gemm_mma<<<grid, 256, 65536>>>(a2cat, b2cat, h2, NN_NODES, 384, 128, // 9
                                       attn_l2, attn_r2, el2, er2, 1);
    }
    agg_k<1, 1, false><<<cdiv(NN_NODES * 32, 256), 256>>>(                   // 10
        h2, el2, er2, bias2, row, srcp, out, nullptr);
}

// round 9
// speedup vs baseline: 1.0990x; 1.0236x over previous
#include <cuda_runtime.h>
#include <cuda_bf16.h>
#include <math_constants.h>
#include <cstdint>

#define NN_NODES 20000
#define EE_EDGES 320000
#define FF 128
#define HH1 3

// ---------------- scratch (static device allocations) ----------------
__device__ float g_h1[NN_NODES * HH1 * FF];
__device__ float g_h2[NN_NODES * FF];
__device__ float g_el1[NN_NODES * 4];
__device__ float g_er1[NN_NODES * 4];
__device__ float g_el2[NN_NODES];
__device__ float g_er2[NN_NODES];
__device__ int   g_row[NN_NODES + 1];
__device__ int   g_cursor[NN_NODES];
__device__ int   g_srcp[EE_EDGES];
__device__ int   g_bsums[64];
__device__ __align__(16) __nv_bfloat16 g_a1cat[NN_NODES * 256];
__device__ __align__(16) __nv_bfloat16 g_a2cat[(size_t)NN_NODES * 768];
__device__ __align__(16) __nv_bfloat16 g_b1cat[384 * 384];
__device__ __align__(16) __nv_bfloat16 g_b2cat[128 * 1152];

// ---------------- helpers ----------------
__device__ __forceinline__ uint32_t smem_u32(const void* p) {
    uint32_t a;
    asm("{ .reg .u64 t; cvta.to.shared.u64 t, %1; cvt.u32.u64 %0, t; }" : "=r"(a) : "l"(p));
    return a;
}
#define LDSM_X4(r0, r1, r2, r3, addr) \
    asm volatile("ldmatrix.sync.aligned.m8n8.x4.shared.b16 {%0,%1,%2,%3}, [%4];" \
                 : "=r"(r0), "=r"(r1), "=r"(r2), "=r"(r3) : "r"(addr))

__device__ __forceinline__ void mma16816(float* d, const uint32_t* a, const uint32_t* b) {
    asm volatile(
        "mma.sync.aligned.m16n8k16.row.col.f32.bf16.bf16.f32 "
        "{%0,%1,%2,%3}, {%4,%5,%6,%7}, {%8,%9}, {%0,%1,%2,%3};"
        : "+f"(d[0]), "+f"(d[1]), "+f"(d[2]), "+f"(d[3])
        : "r"(a[0]), "r"(a[1]), "r"(a[2]), "r"(a[3]), "r"(b[0]), "r"(b[1]));
}
__device__ __forceinline__ void cp16(uint32_t saddr, const void* g, uint32_t sz) {
    asm volatile("cp.async.cg.shared.global [%0], [%1], 16, %2;"
                 :: "r"(saddr), "l"(g), "r"(sz) : "memory");
}
#define CP_COMMIT() asm volatile("cp.async.commit_group;" ::: "memory")
#define CP_WAIT1()  asm volatile("cp.async.wait_group 1;" ::: "memory")

// ---------------- bf16 mma.sync GEMM, 3-stage cp.async, 1 barrier/chunk ----------------
// C[M,NCOLS] = A'[M,3K] @ B[NCOLS,3K]^T, A'[.,k'] = A[., k'<K ? k' : k'-K] (A stored [M,2K]).
// Template MROWS: CTA M-tile (128 or 64). 8 warps: 2 (m) x 4 (n); warp tile (MROWS/2) x 32.
// blockIdx.y = 128-col chunk = head; emits el/er from fp32 accumulators.
template <int MROWS>
__global__ __launch_bounds__(256) void gemm_mma(const __nv_bfloat16* __restrict__ A,
                                                const __nv_bfloat16* __restrict__ B,
                                                float* __restrict__ C,
                                                int M, int K, int NCOLS,
                                                const float* __restrict__ al,
                                                const float* __restrict__ ar,
                                                float* __restrict__ el,
                                                float* __restrict__ er, int st) {
    extern __shared__ __align__(16) uint8_t smem[];  // 3 stages of [A MROWS*128 | B 16384]
    constexpr int ASTAGE = MROWS * 128;
    constexpr int STAGE = ASTAGE + 16384;
    constexpr int MT = MROWS / 32;          // 16-row m-tiles per warp
    constexpr int AP = MROWS / 32;          // A cp16 chunks per thread
    const int tid = threadIdx.x, lane = tid & 31, wid = tid >> 5;
    const int bm = blockIdx.x, bn = blockIdx.y;
    const int wm = (wid & 1) * (MROWS / 2), wn = (wid >> 1) * 32;
    const uint32_t sbase = smem_u32(smem);
    const int Kp = 3 * K, Ald = 2 * K;

    float acc[MT][4][4];
    #pragma unroll
    for (int i = 0; i < MT; i++)
        #pragma unroll
        for (int j = 0; j < 4; j++)
            #pragma unroll
            for (int q = 0; q < 4; q++) acc[i][j][q] = 0.f;

    const int lrow = ((lane >> 3) & 1) * 8 + (lane & 7);
    const int lch = lane >> 4;

    // hoisted ldmatrix row components
    uint32_t aro[MT], arx[MT], bro[2], brx[2];
    #pragma unroll
    for (int mt = 0; mt < MT; mt++) {
        int r = wm + mt * 16 + lrow;
        aro[mt] = (uint32_t)(r * 128);
        arx[mt] = (uint32_t)(r & 7);
    }
    #pragma unroll
    for (int h = 0; h < 2; h++) {
        int r = wn + h * 16 + lrow;
        bro[h] = (uint32_t)(r * 128);
        brx[h] = (uint32_t)(r & 7);
    }

    // per-thread cp.async coords
    int alr[AP], alc[AP];
    uint32_t aso[AP];
    #pragma unroll
    for (int p = 0; p < AP; p++) {
        int g = tid + p * 256;
        alr[p] = g >> 3;
        alc[p] = g & 7;
        aso[p] = (uint32_t)(alr[p] * 128 + ((alc[p] ^ (alr[p] & 7)) << 4));
    }
    int blr[4], blc[4];
    uint32_t bso[4];
    #pragma unroll
    for (int p = 0; p < 4; p++) {
        int g = tid + p * 256;
        blr[p] = g >> 3;
        blc[p] = g & 7;
        bso[p] = (uint32_t)(blr[p] * 128 + ((blc[p] ^ (blr[p] & 7)) << 4));
    }

    auto issue = [&](int stage, int kn) {
        int abase = (kn < K) ? kn : kn - K;
        uint32_t sa = sbase + stage * STAGE;
        uint32_t sb = sa + ASTAGE;
        #pragma unroll
        for (int p = 0; p < AP; p++) {
            int gr = bm * MROWS + alr[p];
            cp16(sa + aso[p], A + (size_t)gr * Ald + abase + alc[p] * 8,
                 (gr < M) ? 16u : 0u);
        }
        #pragma unroll
        for (int p = 0; p < 4; p++)
            cp16(sb + bso[p], B + (size_t)(bn * 128 + blr[p]) * Kp + kn + blc[p] * 8, 16u);
        CP_COMMIT();
    };

    issue(0, 0);
    issue(1, 64);

    const int nchunks = Kp >> 6;
    for (int ck = 0; ck < nchunks; ck++) {
        CP_WAIT1();
        __syncthreads();  // stage ck visible; stage (ck+2)%3 free (consumed last iter)
        if (ck + 2 < nchunks) issue((ck + 2) % 3, (ck + 2) * 64);
        else CP_COMMIT();
        uint32_t sAb = sbase + (ck % 3) * STAGE;
        uint32_t sBb = sAb + ASTAGE;
        #pragma unroll
        for (int ks = 0; ks < 4; ks++) {
            const uint32_t c = (uint32_t)(ks * 2 + lch);
            uint32_t af[MT][4];
            #pragma unroll
            for (int mt = 0; mt < MT; mt++)
                LDSM_X4(af[mt][0], af[mt][1], af[mt][2], af[mt][3],
                        sAb + aro[mt] + ((c ^ arx[mt]) << 4));
            uint32_t bf[4][2];
            #pragma unroll
            for (int h = 0; h < 2; h++) {
                uint32_t t0, t1, t2, t3;
                LDSM_X4(t0, t1, t2, t3, sBb + bro[h] + ((c ^ brx[h]) << 4));
                bf[h * 2 + 0][0] = t0; bf[h * 2 + 0][1] = t2;
                bf[h * 2 + 1][0] = t1; bf[h * 2 + 1][1] = t3;
            }
            #pragma unroll
            for (int mt = 0; mt < MT; mt++)
                #pragma unroll
                for (int nt = 0; nt < 4; nt++)
                    mma16816(acc[mt][nt], af[mt], bf[nt]);
        }
        // no bottom barrier: top-of-next-iter sync protects buffer reuse
    }
    __syncthreads();

    // ---- C write + fused score partials ----
    float ps[MT][4];
    #pragma unroll
    for (int mt = 0; mt < MT; mt++) {
        int gr0 = bm * MROWS + wm + mt * 16 + (lane >> 2);
        float pl0 = 0.f, pr0 = 0.f, pl1 = 0.f, pr1 = 0.f;
        #pragma unroll
        for (int nt = 0; nt < 4; nt++) {
            int col = wn + nt * 8 + (lane & 3) * 2;
            int gc = bn * 128 + col;
            if (gr0 < M)
                *(float2*)(C + (size_t)gr0 * NCOLS + gc) =
                    make_float2(acc[mt][nt][0], acc[mt][nt][1]);
            if (gr0 + 8 < M)
                *(float2*)(C + (size_t)(gr0 + 8) * NCOLS + gc) =
                    make_float2(acc[mt][nt][2], acc[mt][nt][3]);
            float a0 = al[gc], a1 = al[gc + 1];
            float b0 = ar[gc], b1 = ar[gc + 1];
            pl0 += acc[mt][nt][0] * a0 + acc[mt][nt][1] * a1;
            pr0 += acc[mt][nt][0] * b0 + acc[mt][nt][1] * b1;
            pl1 += acc[mt][nt][2] * a0 + acc[mt][nt][3] * a1;
            pr1 += acc[mt][nt][2] * b0 + acc[mt][nt][3] * b1;
        }
        #pragma unroll
        for (int o = 1; o <= 2; o <<= 1) {
            pl0 += __shfl_xor_sync(0xffffffffu, pl0, o);
            pr0 += __shfl_xor_sync(0xffffffffu, pr0, o);
            pl1 += __shfl_xor_sync(0xffffffffu, pl1, o);
            pr1 += __shfl_xor_sync(0xffffffffu, pr1, o);
        }
        ps[mt][0] = pl0; ps[mt][1] = pr0; ps[mt][2] = pl1; ps[mt][3] = pr1;
    }
    __syncthreads();
    float (*s_sl)[4] = (float(*)[4])smem;
    float (*s_sr)[4] = (float(*)[4])(smem + MROWS * 16);
    int wn4 = wid >> 1;
    if ((lane & 3) == 0) {
        #pragma unroll
        for (int mt = 0; mt < MT; mt++) {
            int lr0 = wm + mt * 16 + (lane >> 2);
            s_sl[lr0][wn4] = ps[mt][0];
            s_sr[lr0][wn4] = ps[mt][1];
            s_sl[lr0 + 8][wn4] = ps[mt][2];
            s_sr[lr0 + 8][wn4] = ps[mt][3];
        }
    }
    __syncthreads();
    if (tid < MROWS) {
        int row = bm * MROWS + tid;
        if (row < M) {
            float sl = s_sl[tid][0] + s_sl[tid][1] + s_sl[tid][2] + s_sl[tid][3];
            float sr = s_sr[tid][0] + s_sr[tid][1] + s_sr[tid][2] + s_sr[tid][3];
            el[row * st + bn] = sl;
            er[row * st + bn] = sr;
        }
    }
}

// ---------------- merged prep ----------------
__global__ void prep_all(const float* __restrict__ feats, const float* __restrict__ W1,
                         const float* __restrict__ W2, __nv_bfloat16* __restrict__ a1,
                         __nv_bfloat16* __restrict__ b1, __nv_bfloat16* __restrict__ b2) {
    int i = blockIdx.x * blockDim.x + threadIdx.x;
    const int SA = NN_NODES * FF;
    const int S1 = 384 * 384;
    if (i < SA) {
        int n = i >> 7, k = i & 127;
        float v = feats[i];
        __nv_bfloat16 h = __float2bfloat16(v);
        __nv_bfloat16 l = __float2bfloat16(v - __bfloat162float(h));
        size_t base = (size_t)n * 256 + k;
        a1[base] = h;
        a1[base + 128] = l;
    } else if (i < SA + S1) {
        int j = i - SA;
        int n = j / 384, kp = j % 384;
        int k = kp & 127;
        float v = W1[k * 384 + n];
        __nv_bfloat16 h = __float2bfloat16(v);
        __nv_bfloat16 l = __float2bfloat16(v - __bfloat162float(h));
        b1[j] = (kp < 128) ? h : ((kp < 256) ? l : h);
    } else if (i < SA + S1 + 128 * 1152) {
        int j = i - SA - S1;
        int n = j / 1152, kp = j % 1152;
        int k = kp % 384;
        float v = W2[k * 128 + n];
        __nv_bfloat16 h = __float2bfloat16(v);
        __nv_bfloat16 l = __float2bfloat16(v - __bfloat162float(h));
        b2[j] = (kp < 384) ? h : ((kp < 768) ? l : h);
    }
}

// ---------------- CSR build ----------------
__global__ void zero_counts_k(int* row) {
    int i = blockIdx.x * blockDim.x + threadIdx.x;
    if (i <= NN_NODES) row[i] = 0;
}
__global__ void count_k(const int* __restrict__ dst, int* row) {
    int e = blockIdx.x * blockDim.x + threadIdx.x;
    if (e < EE_EDGES) atomicAdd(&row[dst[e]], 1);
}
__global__ void scan_block_k(int* __restrict__ row, int* __restrict__ bsums, int n) {
    __shared__ int sm[512];
    int i = blockIdx.x * 512 + threadIdx.x;
    int v = (i < n) ? row[i] : 0;
    sm[threadIdx.x] = v;
    __syncthreads();
    #pragma unroll
    for (int off = 1; off < 512; off <<= 1) {
        int t = (threadIdx.x >= off) ? sm[threadIdx.x - off] : 0;
        __syncthreads();
        sm[threadIdx.x] += t;
        __syncthreads();
    }
    int incl = sm[threadIdx.x];
    if (i < n) row[i] = incl - v;
    if (threadIdx.x == 511) bsums[blockIdx.x] = incl;
}
__global__ void scan_add_k(int* __restrict__ row, const int* __restrict__ bsums,
                           int* __restrict__ cursor, int n, int nb) {
    __shared__ int sb[65];
    int tid = threadIdx.x;
    if (tid == 0) sb[0] = 0;
    if (tid < 64) {
        int v = (tid < nb) ? bsums[tid] : 0;
        int lane = tid & 31;
        #pragma unroll
        for (int o = 1; o < 32; o <<= 1) {
            int t = __shfl_up_sync(0xffffffffu, v, o);
            if (lane >= o) v += t;
        }
        sb[tid + 1] = v;
    }
    __syncthreads();
    if (tid >= 32 && tid < 64) sb[tid + 1] += sb[32];
    __syncthreads();
    int i = blockIdx.x * blockDim.x + tid;
    if (i < n) {
        int v = row[i] + sb[i >> 9];
        row[i] = v;
        cursor[i] = v;
    }
    if (i == 0) row[n] = EE_EDGES;
}
__global__ void scatter_k(const int* __restrict__ src, const int* __restrict__ dst,
                          int* cursor, int* __restrict__ srcp) {
    int e = blockIdx.x * blockDim.x + threadIdx.x;
    if (e < EE_EDGES) {
        int p = atomicAdd(&cursor[dst[e]], 1);
        srcp[p] = src[e];
    }
}

// ---------------- aggregation, fp32 gathers, inline exp-weights: warp per (dst, head) ----------------
template <int HEADS, int ST, bool BF16OUT>
__global__ void agg_k(const float* __restrict__ hfeat, const float* __restrict__ el,
                      const float* __restrict__ er, const float* __restrict__ bias,
                      const int* __restrict__ row, const int* __restrict__ srcp,
                      float* __restrict__ out, __nv_bfloat16* __restrict__ ocat) {
    int wg = (blockIdx.x * blockDim.x + threadIdx.x) >> 5;
    int lane = threadIdx.x & 31;
    if (wg >= NN_NODES * HEADS) return;
    int d = wg / HEADS, h = wg - d * HEADS;
    int s0 = row[d], s1 = row[d + 1];
    float erd = er[d * ST + h];

    float4 acc = make_float4(0.f, 0.f, 0.f, 0.f);
    float den = 0.f;
    #pragma unroll 2
    for (int i = s0; i < s1; ++i) {
        int s = srcp[i];
        float e = el[s * ST + h] + erd;
        e = (e > 0.f) ? e : 0.2f * e;
        float wt = __expf(e);
        den += wt;
        float4 v = *(const float4*)(hfeat + (size_t)s * (HEADS * 128) + h * 128 + lane * 4);
        acc.x += wt * v.x;
        acc.y += wt * v.y;
        acc.z += wt * v.z;
        acc.w += wt * v.w;
    }
    float inv = 1.0f / den;
    float4 b4 = *(const float4*)(bias + h * 128 + lane * 4);
    float r[4] = {acc.x * inv + b4.x, acc.y * inv + b4.y,
                  acc.z * inv + b4.z, acc.w * inv + b4.w};
    if (BF16OUT) {
        __nv_bfloat16 hv[4], lv[4];
        #pragma unroll
        for (int q = 0; q < 4; q++) {
            hv[q] = __float2bfloat16(r[q]);
            lv[q] = __float2bfloat16(r[q] - __bfloat162float(hv[q]));
        }
        size_t base = (size_t)d * 768 + h * 128 + lane * 4;
        *(uint2*)(ocat + base) = *(uint2*)hv;
        *(uint2*)(ocat + base + 384) = *(uint2*)lv;
    } else {
        *(float4*)(out + (size_t)d * (HEADS * 128) + h * 128 + lane * 4) =
            make_float4(r[0], r[1], r[2], r[3]);
    }
}

// ---------------- launch ----------------
static inline int cdiv(int a, int b) { return (a + b - 1) / b; }

extern "C" void kernel_launch(void* const* d_in, const int* in_sizes, int n_in,
                              void* d_out, int out_size) {
    const float* feats   = (const float*)d_in[0];
    const float* W1      = (const float*)d_in[1];
    const float* attn_l1 = (const float*)d_in[2];
    const float* attn_r1 = (const float*)d_in[3];
    const float* bias1   = (const float*)d_in[4];
    const float* W2      = (const float*)d_in[5];
    const float* attn_l2 = (const float*)d_in[6];
    const float* attn_r2 = (const float*)d_in[7];
    const float* bias2   = (const float*)d_in[8];
    const int*   src     = (const int*)d_in[9];
    const int*   dst     = (const int*)d_in[10];
    float* out = (float*)d_out;

    float *h1, *h2, *el1, *er1, *el2, *er2;
    int *row, *cursor, *srcp, *bsums;
    __nv_bfloat16 *a1cat, *a2cat, *b1cat, *b2cat;
    cudaGetSymbolAddress((void**)&h1, g_h1);
    cudaGetSymbolAddress((void**)&h2, g_h2);
    cudaGetSymbolAddress((void**)&el1, g_el1);
    cudaGetSymbolAddress((void**)&er1, g_er1);
    cudaGetSymbolAddress((void**)&el2, g_el2);
    cudaGetSymbolAddress((void**)&er2, g_er2);
    cudaGetSymbolAddress((void**)&row, g_row);
    cudaGetSymbolAddress((void**)&cursor, g_cursor);
    cudaGetSymbolAddress((void**)&srcp, g_srcp);
    cudaGetSymbolAddress((void**)&bsums, g_bsums);
    cudaGetSymbolAddress((void**)&a1cat, g_a1cat);
    cudaGetSymbolAddress((void**)&a2cat, g_a2cat);
    cudaGetSymbolAddress((void**)&b1cat, g_b1cat);
    cudaGetSymbolAddress((void**)&b2cat, g_b2cat);

    static cudaStream_t s2 = nullptr;
    static cudaEvent_t evFork = nullptr, evJoin = nullptr;
    static bool attrDone = false;
    if (!s2) {
        cudaStreamCreateWithFlags(&s2, cudaStreamNonBlocking);
        cudaEventCreateWithFlags(&evFork, cudaEventDisableTiming);
        cudaEventCreateWithFlags(&evJoin, cudaEventDisableTiming);
    }
    if (!attrDone) {
        cudaFuncSetAttribute(gemm_mma<128>, cudaFuncAttributeMaxDynamicSharedMemorySize,
                             3 * (128 * 128 + 16384));
        cudaFuncSetAttribute(gemm_mma<64>, cudaFuncAttributeMaxDynamicSharedMemorySize,
                             3 * (64 * 128 + 16384));
        attrDone = true;
    }

    const int nb = cdiv(NN_NODES, 512);

    // fork CSR head on side stream
    cudaEventRecord(evFork, 0);
    cudaStreamWaitEvent(s2, evFork, 0);
    zero_counts_k<<<cdiv(NN_NODES + 1, 256), 256, 0, s2>>>(row);             // 1
    count_k<<<cdiv(EE_EDGES, 256), 256, 0, s2>>>(dst, row);                  // 2
    prep_all<<<cdiv(NN_NODES * FF + 384 * 384 + 128 * 1152, 256), 256>>>(    // 3
        feats, W1, W2, a1cat, b1cat, b2cat);
    {
        dim3 grid(cdiv(NN_NODES, 128), 3);
        gemm_mma<128><<<grid, 256, 3 * (128 * 128 + 16384)>>>(               // 4 (profiled)
            a1cat, b1cat, h1, NN_NODES, 128, 384, attn_l1, attn_r1, el1, er1, 4);
    }
    scan_block_k<<<nb, 512, 0, s2>>>(row, bsums, NN_NODES);                  // 5
    scan_add_k<<<cdiv(NN_NODES, 256), 256, 0, s2>>>(row, bsums, cursor, NN_NODES, nb); // 6
    scatter_k<<<cdiv(EE_EDGES, 256), 256, 0, s2>>>(src, dst, cursor, srcp);  // 7
    cudaEventRecord(evJoin, s2);

    cudaStreamWaitEvent(0, evJoin, 0);
    agg_k<HH1, 4, true><<<cdiv(NN_NODES * HH1 * 32, 256), 256>>>(            // 8
        h1, el1, er1, bias1, row, srcp, nullptr, a2cat);

    {
        dim3 grid(cdiv(NN_NODES, 64), 1);
        gemm_mma<64><<<grid, 256, 3 * (64 * 128 + 16384)>>>(                 // 9
            a2cat, b2cat, h2, NN_NODES, 384, 128, attn_l2, attn_r2, el2, er2, 1);
    }
    agg_k<1, 1, false><<<cdiv(NN_NODES * 32, 256), 256>>>(                   // 10
        h2, el2, er2, bias2, row, srcp, out, nullptr);
}

// round 10
// speedup vs baseline: 1.2380x; 1.1265x over previous
#include <cuda_runtime.h>
#include <cuda_fp16.h>
#include <math_constants.h>
#include <cstdint>

#define NN_NODES 20000
#define EE_EDGES 320000
#define FF 128
#define HH1 3

// ---------------- scratch (static device allocations) ----------------
__device__ float g_h1[NN_NODES * HH1 * FF];
__device__ float g_h2[NN_NODES * FF];
__device__ float g_el1[NN_NODES * 4];
__device__ float g_er1[NN_NODES * 4];
__device__ float g_el2[NN_NODES];
__device__ float g_er2[NN_NODES];
__device__ int   g_row[NN_NODES + 1];
__device__ int   g_cursor[NN_NODES];
__device__ int   g_srcp[EE_EDGES];
__device__ int   g_bsums[64];
// A operands [M, 2K] = exact fp16 (hi | lo); B operands [NCOLS, K] = fp16(W^T)
__device__ __align__(16) __half g_a1cat[NN_NODES * 256];
__device__ __align__(16) __half g_a2cat[(size_t)NN_NODES * 768];
__device__ __align__(16) __half g_b1cat[384 * 128];
__device__ __align__(16) __half g_b2cat[128 * 384];

// ---------------- helpers ----------------
__device__ __forceinline__ uint32_t smem_u32(const void* p) {
    uint32_t a;
    asm("{ .reg .u64 t; cvta.to.shared.u64 t, %1; cvt.u32.u64 %0, t; }" : "=r"(a) : "l"(p));
    return a;
}
#define LDSM_X4(r0, r1, r2, r3, addr) \
    asm volatile("ldmatrix.sync.aligned.m8n8.x4.shared.b16 {%0,%1,%2,%3}, [%4];" \
                 : "=r"(r0), "=r"(r1), "=r"(r2), "=r"(r3) : "r"(addr))

__device__ __forceinline__ void mma16816(float* d, const uint32_t* a, const uint32_t* b) {
    asm volatile(
        "mma.sync.aligned.m16n8k16.row.col.f32.f16.f16.f32 "
        "{%0,%1,%2,%3}, {%4,%5,%6,%7}, {%8,%9}, {%0,%1,%2,%3};"
        : "+f"(d[0]), "+f"(d[1]), "+f"(d[2]), "+f"(d[3])
        : "r"(a[0]), "r"(a[1]), "r"(a[2]), "r"(a[3]), "r"(b[0]), "r"(b[1]));
}
__device__ __forceinline__ void cp16(uint32_t saddr, const void* g, uint32_t sz) {
    asm volatile("cp.async.cg.shared.global [%0], [%1], 16, %2;"
                 :: "r"(saddr), "l"(g), "r"(sz) : "memory");
}
#define CP_COMMIT() asm volatile("cp.async.commit_group;" ::: "memory")
#define CP_WAIT1()  asm volatile("cp.async.wait_group 1;" ::: "memory")

// ---------------- fp16 mma.sync GEMM, 2-product, 3-stage cp.async ----------------
// C[M,NCOLS] = A[M,2K] @ B'[NCOLS,2K]^T where B'[., k'] = B[., k' mod K] (B stored [NCOLS,K]).
// A = (hi|lo) exact fp16 split, so C = A_fp32 @ fp16(B)^T with fp32 accumulate.
// Template MROWS: CTA M-tile. blockIdx.y = 128-col chunk = head; emits fused el/er.
template <int MROWS>
__global__ __launch_bounds__(256) void gemm_mma(const __half* __restrict__ A,
                                                const __half* __restrict__ B,
                                                float* __restrict__ C,
                                                int M, int K, int NCOLS,
                                                const float* __restrict__ al,
                                                const float* __restrict__ ar,
                                                float* __restrict__ el,
                                                float* __restrict__ er, int st) {
    extern __shared__ __align__(16) uint8_t smem[];  // 3 stages of [A MROWS*128 | B 16384]
    constexpr int ASTAGE = MROWS * 128;
    constexpr int STAGE = ASTAGE + 16384;
    constexpr int MT = MROWS / 32;
    constexpr int AP = MROWS / 32;
    const int tid = threadIdx.x, lane = tid & 31, wid = tid >> 5;
    const int bm = blockIdx.x, bn = blockIdx.y;
    const int wm = (wid & 1) * (MROWS / 2), wn = (wid >> 1) * 32;
    const uint32_t sbase = smem_u32(smem);
    const int Kp = 2 * K;  // A row width (elements) and total K' extent

    float acc[MT][4][4];
    #pragma unroll
    for (int i = 0; i < MT; i++)
        #pragma unroll
        for (int j = 0; j < 4; j++)
            #pragma unroll
            for (int q = 0; q < 4; q++) acc[i][j][q] = 0.f;

    const int lrow = ((lane >> 3) & 1) * 8 + (lane & 7);
    const int lch = lane >> 4;

    uint32_t aro[MT], arx[MT], bro[2], brx[2];
    #pragma unroll
    for (int mt = 0; mt < MT; mt++) {
        int r = wm + mt * 16 + lrow;
        aro[mt] = (uint32_t)(r * 128);
        arx[mt] = (uint32_t)(r & 7);
    }
    #pragma unroll
    for (int h = 0; h < 2; h++) {
        int r = wn + h * 16 + lrow;
        bro[h] = (uint32_t)(r * 128);
        brx[h] = (uint32_t)(r & 7);
    }

    int alr[AP], alc[AP];
    uint32_t aso[AP];
    #pragma unroll
    for (int p = 0; p < AP; p++) {
        int g = tid + p * 256;
        alr[p] = g >> 3;
        alc[p] = g & 7;
        aso[p] = (uint32_t)(alr[p] * 128 + ((alc[p] ^ (alr[p] & 7)) << 4));
    }
    int blr[4], blc[4];
    uint32_t bso[4];
    #pragma unroll
    for (int p = 0; p < 4; p++) {
        int g = tid + p * 256;
        blr[p] = g >> 3;
        blc[p] = g & 7;
        bso[p] = (uint32_t)(blr[p] * 128 + ((blc[p] ^ (blr[p] & 7)) << 4));
    }

    auto issue = [&](int stage, int kn) {
        int bbase = (kn < K) ? kn : kn - K;  // B reused across hi/lo halves
        uint32_t sa = sbase + stage * STAGE;
        uint32_t sb = sa + ASTAGE;
        #pragma unroll
        for (int p = 0; p < AP; p++) {
            int gr = bm * MROWS + alr[p];
            cp16(sa + aso[p], A + (size_t)gr * Kp + kn + alc[p] * 8,
                 (gr < M) ? 16u : 0u);
        }
        #pragma unroll
        for (int p = 0; p < 4; p++)
            cp16(sb + bso[p], B + (size_t)(bn * 128 + blr[p]) * K + bbase + blc[p] * 8, 16u);
        CP_COMMIT();
    };

    issue(0, 0);
    issue(1, 64);

    const int nchunks = Kp >> 6;
    for (int ck = 0; ck < nchunks; ck++) {
        CP_WAIT1();
        __syncthreads();
        if (ck + 2 < nchunks) issue((ck + 2) % 3, (ck + 2) * 64);
        else CP_COMMIT();
        uint32_t sAb = sbase + (ck % 3) * STAGE;
        uint32_t sBb = sAb + ASTAGE;
        #pragma unroll
        for (int ks = 0; ks < 4; ks++) {
            const uint32_t c = (uint32_t)(ks * 2 + lch);
            uint32_t af[MT][4];
            #pragma unroll
            for (int mt = 0; mt < MT; mt++)
                LDSM_X4(af[mt][0], af[mt][1], af[mt][2], af[mt][3],
                        sAb + aro[mt] + ((c ^ arx[mt]) << 4));
            uint32_t bf[4][2];
            #pragma unroll
            for (int h = 0; h < 2; h++) {
                uint32_t t0, t1, t2, t3;
                LDSM_X4(t0, t1, t2, t3, sBb + bro[h] + ((c ^ brx[h]) << 4));
                bf[h * 2 + 0][0] = t0; bf[h * 2 + 0][1] = t2;
                bf[h * 2 + 1][0] = t1; bf[h * 2 + 1][1] = t3;
            }
            #pragma unroll
            for (int mt = 0; mt < MT; mt++)
                #pragma unroll
                for (int nt = 0; nt < 4; nt++)
                    mma16816(acc[mt][nt], af[mt], bf[nt]);
        }
    }
    __syncthreads();

    // ---- C write + fused score partials ----
    float ps[MT][4];
    #pragma unroll
    for (int mt = 0; mt < MT; mt++) {
        int gr0 = bm * MROWS + wm + mt * 16 + (lane >> 2);
        float pl0 = 0.f, pr0 = 0.f, pl1 = 0.f, pr1 = 0.f;
        #pragma unroll
        for (int nt = 0; nt < 4; nt++) {
            int col = wn + nt * 8 + (lane & 3) * 2;
            int gc = bn * 128 + col;
            if (gr0 < M)
                *(float2*)(C + (size_t)gr0 * NCOLS + gc) =
                    make_float2(acc[mt][nt][0], acc[mt][nt][1]);
            if (gr0 + 8 < M)
                *(float2*)(C + (size_t)(gr0 + 8) * NCOLS + gc) =
                    make_float2(acc[mt][nt][2], acc[mt][nt][3]);
            float a0 = al[gc], a1 = al[gc + 1];
            float b0 = ar[gc], b1 = ar[gc + 1];
            pl0 += acc[mt][nt][0] * a0 + acc[mt][nt][1] * a1;
            pr0 += acc[mt][nt][0] * b0 + acc[mt][nt][1] * b1;
            pl1 += acc[mt][nt][2] * a0 + acc[mt][nt][3] * a1;
            pr1 += acc[mt][nt][2] * b0 + acc[mt][nt][3] * b1;
        }
        #pragma unroll
        for (int o = 1; o <= 2; o <<= 1) {
            pl0 += __shfl_xor_sync(0xffffffffu, pl0, o);
            pr0 += __shfl_xor_sync(0xffffffffu, pr0, o);
            pl1 += __shfl_xor_sync(0xffffffffu, pl1, o);
            pr1 += __shfl_xor_sync(0xffffffffu, pr1, o);
        }
        ps[mt][0] = pl0; ps[mt][1] = pr0; ps[mt][2] = pl1; ps[mt][3] = pr1;
    }
    __syncthreads();
    float (*s_sl)[4] = (float(*)[4])smem;
    float (*s_sr)[4] = (float(*)[4])(smem + MROWS * 16);
    int wn4 = wid >> 1;
    if ((lane & 3) == 0) {
        #pragma unroll
        for (int mt = 0; mt < MT; mt++) {
            int lr0 = wm + mt * 16 + (lane >> 2);
            s_sl[lr0][wn4] = ps[mt][0];
            s_sr[lr0][wn4] = ps[mt][1];
            s_sl[lr0 + 8][wn4] = ps[mt][2];
            s_sr[lr0 + 8][wn4] = ps[mt][3];
        }
    }
    __syncthreads();
    if (tid < MROWS) {
        int row = bm * MROWS + tid;
        if (row < M) {
            float sl = s_sl[tid][0] + s_sl[tid][1] + s_sl[tid][2] + s_sl[tid][3];
            float sr = s_sr[tid][0] + s_sr[tid][1] + s_sr[tid][2] + s_sr[tid][3];
            el[row * st + bn] = sl;
            er[row * st + bn] = sr;
        }
    }
}

// ---------------- merged prep: A1 exact fp16 split + fp16 weight transposes ----------------
__global__ void prep_all(const float* __restrict__ feats, const float* __restrict__ W1,
                         const float* __restrict__ W2, __half* __restrict__ a1,
                         __half* __restrict__ b1, __half* __restrict__ b2) {
    int i = blockIdx.x * blockDim.x + threadIdx.x;
    const int SA = NN_NODES * FF;
    const int S1 = 384 * 128;
    const int S2 = 128 * 384;
    if (i < SA) {
        int n = i >> 7, k = i & 127;
        float v = feats[i];
        __half h = __float2half_rn(v);
        __half l = __float2half_rn(v - __half2float(h));
        size_t base = (size_t)n * 256 + k;
        a1[base] = h;
        a1[base + 128] = l;
    } else if (i < SA + S1) {  // B1 = fp16(W1^T) [384, 128]
        int j = i - SA;
        int n = j >> 7, k = j & 127;
        b1[j] = __float2half_rn(W1[k * 384 + n]);
    } else if (i < SA + S1 + S2) {  // B2 = fp16(W2^T) [128, 384]
        int j = i - SA - S1;
        int n = j / 384, k = j % 384;
        b2[j] = __float2half_rn(W2[k * 128 + n]);
    }
}

// ---------------- CSR build ----------------
__global__ void zero_counts_k(int* row) {
    int i = blockIdx.x * blockDim.x + threadIdx.x;
    if (i <= NN_NODES) row[i] = 0;
}
__global__ void count_k(const int* __restrict__ dst, int* row) {
    int e = blockIdx.x * blockDim.x + threadIdx.x;
    if (e < EE_EDGES) atomicAdd(&row[dst[e]], 1);
}
__global__ void scan_block_k(int* __restrict__ row, int* __restrict__ bsums, int n) {
    __shared__ int sm[512];
    int i = blockIdx.x * 512 + threadIdx.x;
    int v = (i < n) ? row[i] : 0;
    sm[threadIdx.x] = v;
    __syncthreads();
    #pragma unroll
    for (int off = 1; off < 512; off <<= 1) {
        int t = (threadIdx.x >= off) ? sm[threadIdx.x - off] : 0;
        __syncthreads();
        sm[threadIdx.x] += t;
        __syncthreads();
    }
    int incl = sm[threadIdx.x];
    if (i < n) row[i] = incl - v;
    if (threadIdx.x == 511) bsums[blockIdx.x] = incl;
}
__global__ void scan_add_k(int* __restrict__ row, const int* __restrict__ bsums,
                           int* __restrict__ cursor, int n, int nb) {
    __shared__ int sb[65];
    int tid = threadIdx.x;
    if (tid == 0) sb[0] = 0;
    if (tid < 64) {
        int v = (tid < nb) ? bsums[tid] : 0;
        int lane = tid & 31;
        #pragma unroll
        for (int o = 1; o < 32; o <<= 1) {
            int t = __shfl_up_sync(0xffffffffu, v, o);
            if (lane >= o) v += t;
        }
        sb[tid + 1] = v;
    }
    __syncthreads();
    if (tid >= 32 && tid < 64) sb[tid + 1] += sb[32];
    __syncthreads();
    int i = blockIdx.x * blockDim.x + tid;
    if (i < n) {
        int v = row[i] + sb[i >> 9];
        row[i] = v;
        cursor[i] = v;
    }
    if (i == 0) row[n] = EE_EDGES;
}
__global__ void scatter_k(const int* __restrict__ src, const int* __restrict__ dst,
                          int* cursor, int* __restrict__ srcp) {
    int e = blockIdx.x * blockDim.x + threadIdx.x;
    if (e < EE_EDGES) {
        int p = atomicAdd(&cursor[dst[e]], 1);
        srcp[p] = src[e];
    }
}

// ---------------- aggregation, fp32 gathers, inline exp-weights: warp per (dst, head) ----------------
template <int HEADS, int ST, bool FP16OUT>
__global__ void agg_k(const float* __restrict__ hfeat, const float* __restrict__ el,
                      const float* __restrict__ er, const float* __restrict__ bias,
                      const int* __restrict__ row, const int* __restrict__ srcp,
                      float* __restrict__ out, __half* __restrict__ ocat) {
    int wg = (blockIdx.x * blockDim.x + threadIdx.x) >> 5;
    int lane = threadIdx.x & 31;
    if (wg >= NN_NODES * HEADS) return;
    int d = wg / HEADS, h = wg - d * HEADS;
    int s0 = row[d], s1 = row[d + 1];
    float erd = er[d * ST + h];

    float4 acc = make_float4(0.f, 0.f, 0.f, 0.f);
    float den = 0.f;
    #pragma unroll 2
    for (int i = s0; i < s1; ++i) {
        int s = srcp[i];
        float e = el[s * ST + h] + erd;
        e = (e > 0.f) ? e : 0.2f * e;
        float wt = __expf(e);
        den += wt;
        float4 v = *(const float4*)(hfeat + (size_t)s * (HEADS * 128) + h * 128 + lane * 4);
        acc.x += wt * v.x;
        acc.y += wt * v.y;
        acc.z += wt * v.z;
        acc.w += wt * v.w;
    }
    float inv = 1.0f / den;
    float4 b4 = *(const float4*)(bias + h * 128 + lane * 4);
    float r[4] = {acc.x * inv + b4.x, acc.y * inv + b4.y,
                  acc.z * inv + b4.z, acc.w * inv + b4.w};
    if (FP16OUT) {
        __half hv[4], lv[4];
        #pragma unroll
        for (int q = 0; q < 4; q++) {
            hv[q] = __float2half_rn(r[q]);
            lv[q] = __float2half_rn(r[q] - __half2float(hv[q]));
        }
        size_t base = (size_t)d * 768 + h * 128 + lane * 4;
        *(uint2*)(ocat + base) = *(uint2*)hv;
        *(uint2*)(ocat + base + 384) = *(uint2*)lv;
    } else {
        *(float4*)(out + (size_t)d * (HEADS * 128) + h * 128 + lane * 4) =
            make_float4(r[0], r[1], r[2], r[3]);
    }
}

// ---------------- launch ----------------
static inline int cdiv(int a, int b) { return (a + b - 1) / b; }

extern "C" void kernel_launch(void* const* d_in, const int* in_sizes, int n_in,
                              void* d_out, int out_size) {
    const float* feats   = (const float*)d_in[0];
    const float* W1      = (const float*)d_in[1];
    const float* attn_l1 = (const float*)d_in[2];
    const float* attn_r1 = (const float*)d_in[3];
    const float* bias1   = (const float*)d_in[4];
    const float* W2      = (const float*)d_in[5];
    const float* attn_l2 = (const float*)d_in[6];
    const float* attn_r2 = (const float*)d_in[7];
    const float* bias2   = (const float*)d_in[8];
    const int*   src     = (const int*)d_in[9];
    const int*   dst     = (const int*)d_in[10];
    float* out = (float*)d_out;

    float *h1, *h2, *el1, *er1, *el2, *er2;
    int *row, *cursor, *srcp, *bsums;
    __half *a1cat, *a2cat, *b1cat, *b2cat;
    cudaGetSymbolAddress((void**)&h1, g_h1);
    cudaGetSymbolAddress((void**)&h2, g_h2);
    cudaGetSymbolAddress((void**)&el1, g_el1);
    cudaGetSymbolAddress((void**)&er1, g_er1);
    cudaGetSymbolAddress((void**)&el2, g_el2);
    cudaGetSymbolAddress((void**)&er2, g_er2);
    cudaGetSymbolAddress((void**)&row, g_row);
    cudaGetSymbolAddress((void**)&cursor, g_cursor);
    cudaGetSymbolAddress((void**)&srcp, g_srcp);
    cudaGetSymbolAddress((void**)&bsums, g_bsums);
    cudaGetSymbolAddress((void**)&a1cat, g_a1cat);
    cudaGetSymbolAddress((void**)&a2cat, g_a2cat);
    cudaGetSymbolAddress((void**)&b1cat, g_b1cat);
    cudaGetSymbolAddress((void**)&b2cat, g_b2cat);

    static cudaStream_t s2 = nullptr;
    static cudaEvent_t evFork = nullptr, evJoin = nullptr;
    static bool attrDone = false;
    if (!s2) {
        cudaStreamCreateWithFlags(&s2, cudaStreamNonBlocking);
        cudaEventCreateWithFlags(&evFork, cudaEventDisableTiming);
        cudaEventCreateWithFlags(&evJoin, cudaEventDisableTiming);
    }
    if (!attrDone) {
        cudaFuncSetAttribute(gemm_mma<128>, cudaFuncAttributeMaxDynamicSharedMemorySize,
                             3 * (128 * 128 + 16384));
        cudaFuncSetAttribute(gemm_mma<64>, cudaFuncAttributeMaxDynamicSharedMemorySize,
                             3 * (64 * 128 + 16384));
        attrDone = true;
    }

    const int nb = cdiv(NN_NODES, 512);

    // fork CSR head on side stream
    cudaEventRecord(evFork, 0);
    cudaStreamWaitEvent(s2, evFork, 0);
    zero_counts_k<<<cdiv(NN_NODES + 1, 256), 256, 0, s2>>>(row);             // 1
    count_k<<<cdiv(EE_EDGES, 256), 256, 0, s2>>>(dst, row);                  // 2
    prep_all<<<cdiv(NN_NODES * FF + 2 * 384 * 128, 256), 256>>>(             // 3
        feats, W1, W2, a1cat, b1cat, b2cat);
    {
        dim3 grid(cdiv(NN_NODES, 128), 3);
        gemm_mma<128><<<grid, 256, 3 * (128 * 128 + 16384)>>>(               // 4 (profiled)
            a1cat, b1cat, h1, NN_NODES, 128, 384, attn_l1, attn_r1, el1, er1, 4);
    }
    scan_block_k<<<nb, 512, 0, s2>>>(row, bsums, NN_NODES);                  // 5
    scan_add_k<<<cdiv(NN_NODES, 256), 256, 0, s2>>>(row, bsums, cursor, NN_NODES, nb); // 6
    scatter_k<<<cdiv(EE_EDGES, 256), 256, 0, s2>>>(src, dst, cursor, srcp);  // 7
    cudaEventRecord(evJoin, s2);

    cudaStreamWaitEvent(0, evJoin, 0);
    agg_k<HH1, 4, true><<<cdiv(NN_NODES * HH1 * 32, 256), 256>>>(            // 8
        h1, el1, er1, bias1, row, srcp, nullptr, a2cat);

    {
        dim3 grid(cdiv(NN_NODES, 64), 1);
        gemm_mma<64><<<grid, 256, 3 * (64 * 128 + 16384)>>>(                 // 9
            a2cat, b2cat, h2, NN_NODES, 384, 128, attn_l2, attn_r2, el2, er2, 1);
    }
    agg_k<1, 1, false><<<cdiv(NN_NODES * 32, 256), 256>>>(                   // 10
        h2, el2, er2, bias2, row, srcp, out, nullptr);
}